// round 7
// baseline (speedup 1.0000x reference)
#include <cuda_runtime.h>
#include <math.h>

#define S_LEN    4096
#define B_SZ     8
#define HID      768
#define HS_DIM   256   // HIDDEN/3
#define NFREQ    384   // HID/2
#define HS_NFREQ 128   // HS_DIM/2

// hs_pe table: 4096 x 256 floats = 4 MB (L2-resident)
__device__ float g_hs_pe[S_LEN * HS_DIM];

// ---------------------------------------------------------------------------
// Accurate sincos for |ang| up to ~5000: 3-term Cody-Waite 2*pi reduction
// then MUFU sincos.
// ---------------------------------------------------------------------------
__device__ __forceinline__ void sincos_red(float ang, float* s, float* c) {
    const double TWO_PI_D = 6.283185307179586476925286766559;
    const float  P1 = 6.28125f;
    const float  P2 = (float)(TWO_PI_D - (double)6.28125f);
    const float  P3 = (float)(TWO_PI_D - (double)6.28125f - (double)((float)(TWO_PI_D - (double)6.28125f)));
    const float  INV2PI = 0.15915494309189535f;
    float k = rintf(ang * INV2PI);
    float r = fmaf(-k, P1, ang);
    r = fmaf(-k, P2, r);
    r = fmaf(-k, P3, r);
    __sincosf(r, s, c);
}

// ---------------------------------------------------------------------------
// Prologue: hs_pe = sin_table(256)[:4096]. Thread owns one freq, 16 positions
// (expf hoisted). ~1.4us.
// ---------------------------------------------------------------------------
__global__ __launch_bounds__(128) void hs_pe_kernel() {
    const int k  = threadIdx.x;          // 0..127 frequency
    const int p0 = blockIdx.x * 16;
    const float CEXP = (float)(-9.210340371976184 / 256.0); // -ln(1e4)/256
    float div = expf((float)(2 * k) * CEXP);
    float2* out = (float2*)g_hs_pe;
#pragma unroll
    for (int j = 0; j < 16; j++) {
        int p = p0 + j;
        float sv, cv;
        sincos_red((float)p * div, &sv, &cv);
        out[p * HS_NFREQ + k] = make_float2(sv, cv);
    }
}

// ---------------------------------------------------------------------------
// Main fused kernel: CTA = one sequence position s, 512 threads.
//   16 warps = 8 batch rows x 2 half-row warps (96 float4 each).
//   Half-row split halves the per-warp latency chain and cuts registers
//   (v[3] instead of v[6]) -> 3 CTAs/SM = 75% occupancy.
//   pe[s] computed once into SMEM (1 sincos/thread).
// ---------------------------------------------------------------------------
__global__ __launch_bounds__(512, 3) void emb_ln_kernel(
    const int*   __restrict__ input_ids,     // [8,4096]
    const int*   __restrict__ tok_struct,    // [8,4096,3]
    const int*   __restrict__ token_type,    // [8,4096]
    const float* __restrict__ word_emb,      // [30522,768]
    const float* __restrict__ type_emb,      // [2,768]
    const float* __restrict__ ln_w,          // [768]
    const float* __restrict__ ln_b,          // [768]
    float*       __restrict__ out)           // [8,4096,768]
{
    __shared__ float  s_pe[HID];
    __shared__ float2 s_red[16];             // per-warp partial (sum, sumsq)

    const int s   = blockIdx.x;
    const int tid = threadIdx.x;

    // Phase 1: pe row, one sincos per thread (384 pairs over 512 threads)
    if (tid < NFREQ) {
        const float CEXP = (float)(-9.210340371976184 / 768.0); // -ln(1e4)/768
        float div = expf((float)(2 * tid) * CEXP);
        float sv, cv;
        sincos_red((float)s * div, &sv, &cv);
        s_pe[2 * tid]     = sv;
        s_pe[2 * tid + 1] = cv;
    }
    __syncthreads();

    // Phase 2: warp w -> batch row b = w>>1, half = w&1 (chunks half*3..half*3+2)
    const int warp = tid >> 5;
    const int lane = tid & 31;
    const int b    = warp >> 1;
    const int half = warp & 1;
    const int idx  = b * S_LEN + s;

    const int tok = __ldg(&input_ids[idx]);
    const int tt  = __ldg(&token_type[idx]);
    const int pp  = __ldg(&tok_struct[idx * 3]);    // para_pos

    const float4* wrow  = (const float4*)(word_emb + (size_t)tok * HID);
    const float4* perow = (const float4*)s_pe;
    const float4* hrow  = (const float4*)(g_hs_pe + (size_t)pp * HS_DIM);
    const float4* trow  = (const float4*)(type_emb + tt * HID);

    // struct = concat(g,g,g): chunk i uses hs float4 (i&1)? lane+32 : lane
    float4 h[2];
    h[0] = __ldg(&hrow[lane]);
    h[1] = __ldg(&hrow[lane + 32]);

    const int c0 = half * 3;                 // first chunk for this warp
    float4 v[3];
    float sum = 0.f, sumsq = 0.f;
#pragma unroll
    for (int j = 0; j < 3; j++) {
        const int i = c0 + j;
        const int c = lane + 32 * i;
        float4 w4 = __ldg(&wrow[c]);
        float4 p4 = perow[c];
        float4 t4 = __ldg(&trow[c]);
        float4 h4 = h[i & 1];
        float4 e;
        e.x = (w4.x + h4.x) + (p4.x + t4.x);
        e.y = (w4.y + h4.y) + (p4.y + t4.y);
        e.z = (w4.z + h4.z) + (p4.z + t4.z);
        e.w = (w4.w + h4.w) + (p4.w + t4.w);
        v[j] = e;
        sum   += (e.x + e.y) + (e.z + e.w);
        sumsq += fmaf(e.x, e.x, fmaf(e.y, e.y, fmaf(e.z, e.z, e.w * e.w)));
    }

#pragma unroll
    for (int off = 16; off > 0; off >>= 1) {
        sum   += __shfl_xor_sync(0xFFFFFFFFu, sum,   off);
        sumsq += __shfl_xor_sync(0xFFFFFFFFu, sumsq, off);
    }
    if (lane == 0) s_red[warp] = make_float2(sum, sumsq);
    __syncthreads();

    float2 a0 = s_red[warp & ~1];
    float2 a1 = s_red[warp | 1];
    sum   = a0.x + a1.x;
    sumsq = a0.y + a1.y;

    const float inv_n = 1.0f / 768.0f;
    float mu   = sum * inv_n;
    float var  = fmaf(sumsq, inv_n, -mu * mu);
    var = var < 0.f ? 0.f : var;
    float rstd = rsqrtf(var + 1e-12f);

    const float4* wg4 = (const float4*)ln_w;
    const float4* bi4 = (const float4*)ln_b;
    float4* orow = (float4*)(out + (size_t)idx * HID);
#pragma unroll
    for (int j = 0; j < 3; j++) {
        const int c = lane + 32 * (c0 + j);
        float4 e  = v[j];
        float4 wg = __ldg(&wg4[c]);
        float4 bi = __ldg(&bi4[c]);
        float4 o;
        o.x = fmaf((e.x - mu) * rstd, wg.x, bi.x);
        o.y = fmaf((e.y - mu) * rstd, wg.y, bi.y);
        o.z = fmaf((e.z - mu) * rstd, wg.z, bi.z);
        o.w = fmaf((e.w - mu) * rstd, wg.w, bi.w);
        __stcs(&orow[c], o);   // streaming store: preserve L2 for word_emb
    }
}

// ---------------------------------------------------------------------------
extern "C" void kernel_launch(void* const* d_in, const int* in_sizes, int n_in,
                              void* d_out, int out_size) {
    const int*   input_ids  = (const int*)  d_in[0];
    const int*   tok_struct = (const int*)  d_in[1];
    // d_in[2] = sent_struct_vec (unused by the reference output)
    const int*   token_type = (const int*)  d_in[3];
    const float* word_emb   = (const float*)d_in[4];
    const float* type_emb   = (const float*)d_in[5];
    const float* ln_w       = (const float*)d_in[6];
    const float* ln_b       = (const float*)d_in[7];
    float*       out        = (float*)d_out;

    hs_pe_kernel<<<S_LEN / 16, 128>>>();
    emb_ln_kernel<<<S_LEN, 512>>>(input_ids, tok_struct, token_type,
                                  word_emb, type_emb, ln_w, ln_b, out);
}

// round 8
// speedup vs baseline: 1.3742x; 1.3742x over previous
#include <cuda_runtime.h>
#include <math.h>

#define S_LEN    4096
#define B_SZ     8
#define HID      768
#define HS_DIM   256   // HIDDEN/3
#define NFREQ    384   // HID/2
#define HS_NFREQ 128   // HS_DIM/2

// hs_pe table: 4096 x 256 floats = 4 MB (L2-resident)
__device__ float g_hs_pe[S_LEN * HS_DIM];

// ---------------------------------------------------------------------------
// Accurate sincos for |ang| up to ~5000: 3-term Cody-Waite 2*pi reduction
// then MUFU sincos.
// ---------------------------------------------------------------------------
__device__ __forceinline__ void sincos_red(float ang, float* s, float* c) {
    const double TWO_PI_D = 6.283185307179586476925286766559;
    const float  P1 = 6.28125f;
    const float  P2 = (float)(TWO_PI_D - (double)6.28125f);
    const float  P3 = (float)(TWO_PI_D - (double)6.28125f - (double)((float)(TWO_PI_D - (double)6.28125f)));
    const float  INV2PI = 0.15915494309189535f;
    float k = rintf(ang * INV2PI);
    float r = fmaf(-k, P1, ang);
    r = fmaf(-k, P2, r);
    r = fmaf(-k, P3, r);
    __sincosf(r, s, c);
}

// ---------------------------------------------------------------------------
// Prologue: hs_pe = sin_table(256)[:4096]. Thread owns one freq, 16 positions
// (expf hoisted). ~1.4us.
// ---------------------------------------------------------------------------
__global__ __launch_bounds__(128) void hs_pe_kernel() {
    const int k  = threadIdx.x;          // 0..127 frequency
    const int p0 = blockIdx.x * 16;
    const float CEXP = (float)(-9.210340371976184 / 256.0); // -ln(1e4)/256
    float div = expf((float)(2 * k) * CEXP);
    float2* out = (float2*)g_hs_pe;
#pragma unroll
    for (int j = 0; j < 16; j++) {
        int p = p0 + j;
        float sv, cv;
        sincos_red((float)p * div, &sv, &cv);
        out[p * HS_NFREQ + k] = make_float2(sv, cv);
    }
}

// ---------------------------------------------------------------------------
// Main fused kernel, CHUNK-MAJOR: CTA = one position s, 192 threads.
// Thread t owns float4 column c=t (channels 4c..4c+3) for ALL 8 batch rows.
//   - pe: 2 sincos per thread, in registers (no loads, no smem)
//   - type rows (2), ln_w, ln_b: loaded ONCE per CTA into registers
//   - per row: only word (24wf) + hs (24wf) + store (24wf)
//   - 8 independent word+hs loads per thread -> MLP ~16
// Reduction: value-splitting butterfly (16 shfl for 16 values) + tiny smem.
// ---------------------------------------------------------------------------
#define RED_ROUND(OFF, K)                                                   \
    {                                                                       \
        _Pragma("unroll")                                                   \
        for (int j = 0; j < (K) / 2; j++) {                                 \
            float send = (lane & (OFF)) ? vals[j] : vals[j + (K) / 2];      \
            float recv = __shfl_xor_sync(0xffffffffu, send, (OFF));         \
            float keep = (lane & (OFF)) ? vals[j + (K) / 2] : vals[j];      \
            vals[j] = keep + recv;                                          \
        }                                                                   \
    }

__global__ __launch_bounds__(192) void emb_ln_kernel(
    const int*   __restrict__ input_ids,     // [8,4096]
    const int*   __restrict__ tok_struct,    // [8,4096,3]
    const int*   __restrict__ token_type,    // [8,4096]
    const float* __restrict__ word_emb,      // [30522,768]
    const float* __restrict__ type_emb,      // [2,768]
    const float* __restrict__ ln_w,          // [768]
    const float* __restrict__ ln_b,          // [768]
    float*       __restrict__ out)           // [8,4096,768]
{
    __shared__ float s_red[6 * 16];          // per-warp reduced (sum0..7, sq0..7)
    __shared__ float s_mu[8], s_rstd[8];

    const int s    = blockIdx.x;
    const int tid  = threadIdx.x;
    const int warp = tid >> 5;
    const int lane = tid & 31;
    const int c    = tid;                    // float4 column 0..191
    const int hc   = c & 63;                 // hs column (concat(g,g,g))

    // Row metadata: lanes 0..7 of every warp load, broadcast later via shfl.
    int myTok = 0, myTT = 0, myPP = 0;
    if (lane < 8) {
        int idx = lane * S_LEN + s;
        myTok = __ldg(&input_ids[idx]);
        myTT  = __ldg(&token_type[idx]);
        myPP  = __ldg(&tok_struct[idx * 3]);
    }

    // pe channels 4c..4c+3 = freq pairs k0=2c, k1=2c+1 (computed, not loaded)
    float4 pe4;
    {
        const float CEXP = (float)(-9.210340371976184 / 768.0); // -ln(1e4)/768
        float d0 = expf((float)(4 * c) * CEXP);       // 2*k0
        float d1 = expf((float)(4 * c + 2) * CEXP);   // 2*k1
        sincos_red((float)s * d0, &pe4.x, &pe4.y);
        sincos_red((float)s * d1, &pe4.z, &pe4.w);
    }

    // Per-CTA constant columns
    const float4 t0 = __ldg(((const float4*)type_emb) + c);
    const float4 t1 = __ldg(((const float4*)type_emb) + 192 + c);
    const float4 wg = __ldg(((const float4*)ln_w) + c);
    const float4 bi = __ldg(((const float4*)ln_b) + c);

    const float4* w4p = (const float4*)word_emb;
    const float4* h4p = (const float4*)g_hs_pe;

    float4 v[8];
    float  vals[16];                         // [sum0..7, sq0..7]
#pragma unroll
    for (int r = 0; r < 8; r++) {
        int tok = __shfl_sync(0xffffffffu, myTok, r);
        int pp  = __shfl_sync(0xffffffffu, myPP,  r);
        int tt  = __shfl_sync(0xffffffffu, myTT,  r);
        float4 w4 = __ldg(w4p + (size_t)tok * 192 + c);
        float4 h4 = __ldg(h4p + (size_t)pp * 64 + hc);
        float4 tb;
        tb.x = tt ? t1.x : t0.x;
        tb.y = tt ? t1.y : t0.y;
        tb.z = tt ? t1.z : t0.z;
        tb.w = tt ? t1.w : t0.w;
        float4 e;
        e.x = (w4.x + h4.x) + (pe4.x + tb.x);
        e.y = (w4.y + h4.y) + (pe4.y + tb.y);
        e.z = (w4.z + h4.z) + (pe4.z + tb.z);
        e.w = (w4.w + h4.w) + (pe4.w + tb.w);
        v[r] = e;
        vals[r]     = (e.x + e.y) + (e.z + e.w);
        vals[8 + r] = fmaf(e.x, e.x, fmaf(e.y, e.y, fmaf(e.z, e.z, e.w * e.w)));
    }

    // Value-splitting butterfly: 16 values over 32 lanes in 16 shfl.
    RED_ROUND(16, 16)
    RED_ROUND(8, 8)
    RED_ROUND(4, 4)
    RED_ROUND(2, 2)
    vals[0] += __shfl_xor_sync(0xffffffffu, vals[0], 1);
    // Lane L now holds reduced value index v = (L>>1) & 15.
    if (!(lane & 1)) s_red[warp * 16 + ((lane >> 1) & 15)] = vals[0];
    __syncthreads();

    if (tid < 8) {
        float sum = 0.f, sq = 0.f;
#pragma unroll
        for (int w = 0; w < 6; w++) {
            sum += s_red[w * 16 + tid];
            sq  += s_red[w * 16 + 8 + tid];
        }
        const float inv_n = 1.0f / 768.0f;
        float mu  = sum * inv_n;
        float var = fmaf(sq, inv_n, -mu * mu);
        var = var < 0.f ? 0.f : var;
        s_mu[tid]   = mu;
        s_rstd[tid] = rsqrtf(var + 1e-12f);
    }
    __syncthreads();

    float4* o4 = (float4*)out;
#pragma unroll
    for (int r = 0; r < 8; r++) {
        float mu   = s_mu[r];
        float rstd = s_rstd[r];
        float4 e = v[r], o;
        o.x = fmaf((e.x - mu) * rstd, wg.x, bi.x);
        o.y = fmaf((e.y - mu) * rstd, wg.y, bi.y);
        o.z = fmaf((e.z - mu) * rstd, wg.z, bi.z);
        o.w = fmaf((e.w - mu) * rstd, wg.w, bi.w);
        __stcs(o4 + (size_t)(r * S_LEN + s) * 192 + c, o);  // streaming store
    }
}

// ---------------------------------------------------------------------------
extern "C" void kernel_launch(void* const* d_in, const int* in_sizes, int n_in,
                              void* d_out, int out_size) {
    const int*   input_ids  = (const int*)  d_in[0];
    const int*   tok_struct = (const int*)  d_in[1];
    // d_in[2] = sent_struct_vec (unused by the reference output)
    const int*   token_type = (const int*)  d_in[3];
    const float* word_emb   = (const float*)d_in[4];
    const float* type_emb   = (const float*)d_in[5];
    const float* ln_w       = (const float*)d_in[6];
    const float* ln_b       = (const float*)d_in[7];
    float*       out        = (float*)d_out;

    hs_pe_kernel<<<S_LEN / 16, 128>>>();
    emb_ln_kernel<<<S_LEN, 192>>>(input_ids, tok_struct, token_type,
                                  word_emb, type_emb, ln_w, ln_b, out);
}

// round 9
// speedup vs baseline: 1.5848x; 1.1533x over previous
#include <cuda_runtime.h>
#include <math.h>

#define S_LEN    4096
#define B_SZ     8
#define HID      768
#define HS_DIM   256   // HIDDEN/3
#define NFREQ    384   // HID/2
#define HS_NFREQ 128   // HS_DIM/2

// hs_pe table: 4096 x 256 floats = 4 MB (L2-resident)
__device__ float g_hs_pe[S_LEN * HS_DIM];

// ---------------------------------------------------------------------------
// Accurate sincos for |ang| up to ~5000: 3-term Cody-Waite 2*pi reduction
// then MUFU sincos.
// ---------------------------------------------------------------------------
__device__ __forceinline__ void sincos_red(float ang, float* s, float* c) {
    const double TWO_PI_D = 6.283185307179586476925286766559;
    const float  P1 = 6.28125f;
    const float  P2 = (float)(TWO_PI_D - (double)6.28125f);
    const float  P3 = (float)(TWO_PI_D - (double)6.28125f - (double)((float)(TWO_PI_D - (double)6.28125f)));
    const float  INV2PI = 0.15915494309189535f;
    float k = rintf(ang * INV2PI);
    float r = fmaf(-k, P1, ang);
    r = fmaf(-k, P2, r);
    r = fmaf(-k, P3, r);
    __sincosf(r, s, c);
}

// ---------------------------------------------------------------------------
// Prologue: hs_pe = sin_table(256)[:4096]. Thread owns one freq, 16 positions.
// ---------------------------------------------------------------------------
__global__ __launch_bounds__(128) void hs_pe_kernel() {
    const int k  = threadIdx.x;          // 0..127 frequency
    const int p0 = blockIdx.x * 16;
    const float CEXP = (float)(-9.210340371976184 / 256.0); // -ln(1e4)/256
    float div = expf((float)(2 * k) * CEXP);
    float2* out = (float2*)g_hs_pe;
#pragma unroll
    for (int j = 0; j < 16; j++) {
        int p = p0 + j;
        float sv, cv;
        sincos_red((float)p * div, &sv, &cv);
        out[p * HS_NFREQ + k] = make_float2(sv, cv);
    }
}

// ---------------------------------------------------------------------------
// Main fused kernel, CHUNK-MAJOR, 4 rows/CTA:
// CTA = (position s, batch-group g). Thread t owns float4 column c=t for the
// 4 batch rows 4g..4g+3.
//   - pe: 2 sincos per thread, registers only
//   - type rows, ln params: per-CTA, amortized over 4 rows
//   - per thread: 4 word + 4 hs fully independent gathers (MLP ~8)
//   - v[4]+vals[8] instead of v[8]+vals[16]: launch_bounds(192,6)
//     -> 36 warps/SM (56% occ) vs R8's 21.5.
// Reduction: value-splitting butterfly (8 values in 3.5 rounds) + tiny smem.
// ---------------------------------------------------------------------------
#define RED_ROUND(OFF, K)                                                   \
    {                                                                       \
        _Pragma("unroll")                                                   \
        for (int j = 0; j < (K) / 2; j++) {                                 \
            float send = (lane & (OFF)) ? vals[j] : vals[j + (K) / 2];      \
            float recv = __shfl_xor_sync(0xffffffffu, send, (OFF));         \
            float keep = (lane & (OFF)) ? vals[j + (K) / 2] : vals[j];      \
            vals[j] = keep + recv;                                          \
        }                                                                   \
    }

__global__ __launch_bounds__(192, 6) void emb_ln_kernel(
    const int*   __restrict__ input_ids,     // [8,4096]
    const int*   __restrict__ tok_struct,    // [8,4096,3]
    const int*   __restrict__ token_type,    // [8,4096]
    const float* __restrict__ word_emb,      // [30522,768]
    const float* __restrict__ type_emb,      // [2,768]
    const float* __restrict__ ln_w,          // [768]
    const float* __restrict__ ln_b,          // [768]
    float*       __restrict__ out)           // [8,4096,768]
{
    __shared__ float s_red[6 * 8];           // per-warp reduced (sum0..3, sq0..3)
    __shared__ float s_mu[4], s_rstd[4];

    const int s    = blockIdx.x >> 1;        // position
    const int g    = blockIdx.x & 1;         // batch group: rows 4g..4g+3
    const int tid  = threadIdx.x;
    const int warp = tid >> 5;
    const int lane = tid & 31;
    const int c    = tid;                    // float4 column 0..191
    const int hc   = c & 63;                 // hs column (concat(g,g,g))

    // Row metadata: lanes 0..3 load, broadcast via shfl.
    int myTok = 0, myTT = 0, myPP = 0;
    if (lane < 4) {
        int idx = (g * 4 + lane) * S_LEN + s;
        myTok = __ldg(&input_ids[idx]);
        myTT  = __ldg(&token_type[idx]);
        myPP  = __ldg(&tok_struct[idx * 3]);
    }

    // pe channels 4c..4c+3 (computed, not loaded)
    float4 pe4;
    {
        const float CEXP = (float)(-9.210340371976184 / 768.0); // -ln(1e4)/768
        float d0 = expf((float)(4 * c) * CEXP);
        float d1 = expf((float)(4 * c + 2) * CEXP);
        sincos_red((float)s * d0, &pe4.x, &pe4.y);
        sincos_red((float)s * d1, &pe4.z, &pe4.w);
    }

    // Per-CTA type rows (ln_w/ln_b deliberately loaded AFTER the loop/barrier)
    const float4 t0 = __ldg(((const float4*)type_emb) + c);
    const float4 t1 = __ldg(((const float4*)type_emb) + 192 + c);

    const float4* w4p = (const float4*)word_emb;
    const float4* h4p = (const float4*)g_hs_pe;

    float4 v[4];
    float  vals[8];                          // [sum0..3, sq0..3]
#pragma unroll
    for (int r = 0; r < 4; r++) {
        int tok = __shfl_sync(0xffffffffu, myTok, r);
        int pp  = __shfl_sync(0xffffffffu, myPP,  r);
        int tt  = __shfl_sync(0xffffffffu, myTT,  r);
        float4 w4 = __ldg(w4p + (size_t)tok * 192 + c);
        float4 h4 = __ldg(h4p + (size_t)pp * 64 + hc);
        float4 tb;
        tb.x = tt ? t1.x : t0.x;
        tb.y = tt ? t1.y : t0.y;
        tb.z = tt ? t1.z : t0.z;
        tb.w = tt ? t1.w : t0.w;
        float4 e;
        e.x = (w4.x + h4.x) + (pe4.x + tb.x);
        e.y = (w4.y + h4.y) + (pe4.y + tb.y);
        e.z = (w4.z + h4.z) + (pe4.z + tb.z);
        e.w = (w4.w + h4.w) + (pe4.w + tb.w);
        v[r] = e;
        vals[r]     = (e.x + e.y) + (e.z + e.w);
        vals[4 + r] = fmaf(e.x, e.x, fmaf(e.y, e.y, fmaf(e.z, e.z, e.w * e.w)));
    }

    // Value-splitting butterfly: 8 values over 32 lanes.
    RED_ROUND(16, 8)
    RED_ROUND(8, 4)
    RED_ROUND(4, 2)
    vals[0] += __shfl_xor_sync(0xffffffffu, vals[0], 2);
    vals[0] += __shfl_xor_sync(0xffffffffu, vals[0], 1);
    // Lane L (L&3==0) holds reduced value index (L>>2)&7.
    if ((lane & 3) == 0) s_red[warp * 8 + (lane >> 2)] = vals[0];
    __syncthreads();

    if (tid < 4) {
        float sum = 0.f, sq = 0.f;
#pragma unroll
        for (int w = 0; w < 6; w++) {
            sum += s_red[w * 8 + tid];
            sq  += s_red[w * 8 + 4 + tid];
        }
        const float inv_n = 1.0f / 768.0f;
        float mu  = sum * inv_n;
        float var = fmaf(sq, inv_n, -mu * mu);
        var = var < 0.f ? 0.f : var;
        s_mu[tid]   = mu;
        s_rstd[tid] = rsqrtf(var + 1e-12f);
    }
    __syncthreads();

    // ln params loaded here so they are not live across the gather loop.
    const float4 wg = __ldg(((const float4*)ln_w) + c);
    const float4 bi = __ldg(((const float4*)ln_b) + c);

    float4* o4 = (float4*)out;
#pragma unroll
    for (int r = 0; r < 4; r++) {
        float mu   = s_mu[r];
        float rstd = s_rstd[r];
        float4 e = v[r], o;
        o.x = fmaf((e.x - mu) * rstd, wg.x, bi.x);
        o.y = fmaf((e.y - mu) * rstd, wg.y, bi.y);
        o.z = fmaf((e.z - mu) * rstd, wg.z, bi.z);
        o.w = fmaf((e.w - mu) * rstd, wg.w, bi.w);
        __stcs(o4 + (size_t)((g * 4 + r) * S_LEN + s) * 192 + c, o);
    }
}

// ---------------------------------------------------------------------------
extern "C" void kernel_launch(void* const* d_in, const int* in_sizes, int n_in,
                              void* d_out, int out_size) {
    const int*   input_ids  = (const int*)  d_in[0];
    const int*   tok_struct = (const int*)  d_in[1];
    // d_in[2] = sent_struct_vec (unused by the reference output)
    const int*   token_type = (const int*)  d_in[3];
    const float* word_emb   = (const float*)d_in[4];
    const float* type_emb   = (const float*)d_in[5];
    const float* ln_w       = (const float*)d_in[6];
    const float* ln_b       = (const float*)d_in[7];
    float*       out        = (float*)d_out;

    hs_pe_kernel<<<S_LEN / 16, 128>>>();
    emb_ln_kernel<<<S_LEN * 2, 192>>>(input_ids, tok_struct, token_type,
                                      word_emb, type_emb, ln_w, ln_b, out);
}